// round 16
// baseline (speedup 1.0000x reference)
#include <cuda_runtime.h>
#include <cuda_fp16.h>
#include <cstdint>
#include <cstddef>

#define BB   16
#define T1   512
#define NH   8
#define DK   64
#define EMB  512
#define NPOS 1023
#define BD_LD 1024

// ---------------- scratch (module globals; no runtime allocation) ----------
__device__ float g_Q[BB * T1 * EMB];
__device__ float g_K[BB * T1 * EMB];
__device__ float g_V[BB * T1 * EMB];
__device__ float g_P[BB * NPOS * EMB];
__device__ float g_BD[(size_t)BB * NH * T1 * BD_LD];
__device__ float g_C[BB * T1 * EMB];

// ======================= helpers ===========================================
__device__ __forceinline__ uint32_t smem_u32(const void* p) {
    uint32_t a;
    asm("{ .reg .u64 t; cvta.to.shared.u64 t, %1; cvt.u32.u64 %0, t; }"
        : "=r"(a) : "l"(p));
    return a;
}
__device__ __forceinline__ uint32_t pkhf(__half a, __half b) {
    __half2 t;
    t.x = a; t.y = b;
    return *reinterpret_cast<uint32_t*>(&t);
}
// fp16 hi/lo split: a = hi + lo. hi*hi products exact in fp32 accum.
__device__ __forceinline__ void split4(float4 v, uint2& hi, uint2& lo) {
    __half hx = __float2half_rn(v.x);
    __half hy = __float2half_rn(v.y);
    __half hz = __float2half_rn(v.z);
    __half hw = __float2half_rn(v.w);
    float rx = v.x - __half2float(hx);
    float ry = v.y - __half2float(hy);
    float rz = v.z - __half2float(hz);
    float rw = v.w - __half2float(hw);
    hi = make_uint2(pkhf(hx, hy), pkhf(hz, hw));
    lo = make_uint2(pkhf(__float2half_rn(rx), __float2half_rn(ry)),
                    pkhf(__float2half_rn(rz), __float2half_rn(rw)));
}
__device__ __forceinline__ void ldsm4(uint32_t* r, uint32_t a) {
    asm volatile("ldmatrix.sync.aligned.m8n8.x4.shared.b16 {%0,%1,%2,%3}, [%4];"
                 : "=r"(r[0]), "=r"(r[1]), "=r"(r[2]), "=r"(r[3]) : "r"(a));
}
__device__ __forceinline__ void ldsm2(uint32_t* r, uint32_t a) {
    asm volatile("ldmatrix.sync.aligned.m8n8.x2.shared.b16 {%0,%1}, [%2];"
                 : "=r"(r[0]), "=r"(r[1]) : "r"(a));
}
__device__ __forceinline__ void ldsm2t(uint32_t* r, uint32_t a) {
    asm volatile("ldmatrix.sync.aligned.m8n8.x2.trans.shared.b16 {%0,%1}, [%2];"
                 : "=r"(r[0]), "=r"(r[1]) : "r"(a));
}
__device__ __forceinline__ void mmab(float* c, const uint32_t* a, const uint32_t* b) {
    asm volatile("mma.sync.aligned.m16n8k16.row.col.f32.f16.f16.f32 "
                 "{%0,%1,%2,%3}, {%4,%5,%6,%7}, {%8,%9}, {%0,%1,%2,%3};"
                 : "+f"(c[0]), "+f"(c[1]), "+f"(c[2]), "+f"(c[3])
                 : "r"(a[0]), "r"(a[1]), "r"(a[2]), "r"(a[3]),
                   "r"(b[0]), "r"(b[1]));
}

// ===========================================================================
// Double-buffered GEMM body (fp16 split): C = A B^T (+nbias) (+kbias on A)
// 128x128 tile, BK=32, 8 warps (2x4). use3: 3-term vs 2-term.
// ===========================================================================
#define GB_SET_U32 10240
#define GB_SMEM (2 * GB_SET_U32 * 4)

__device__ __forceinline__ void gemm_body(
    const float* __restrict__ Az, const float* __restrict__ Bz,
    const float* __restrict__ nbias, const float* __restrict__ kb,
    float* __restrict__ Cz, int M, int Brows, int K, int Cld, int Ncap,
    int m0, int n0, uint32_t* S, bool use3)
{
    const int tid = threadIdx.x;
    const int lane = tid & 31, wid = tid >> 5;
    const int wm = wid >> 2, wn = wid & 3;

    const int arow = tid >> 1;
    const int akb  = (tid & 1) * 16;
    const bool aok = (m0 + arow) < M;
    const bool bok = (n0 + arow) < Brows;
    const float* Ap = Az + (size_t)(m0 + arow) * 512 + akb;
    const float* Bp = Bz + (size_t)(n0 + arow) * 512 + akb;

    float acc[4][4][4];
#pragma unroll
    for (int i = 0; i < 4; i++)
#pragma unroll
        for (int j = 0; j < 4; j++)
#pragma unroll
            for (int q = 0; q < 4; q++) acc[i][j][q] = 0.f;

    const uint32_t sB = smem_u32(S);
    const float4 z4 = make_float4(0.f, 0.f, 0.f, 0.f);
    float4 av[4], bv[4];

    auto ldg_chunk = [&](int kt) {
#pragma unroll
        for (int q = 0; q < 4; q++) {
            av[q] = aok ? *(const float4*)(Ap + kt + q * 4) : z4;
            bv[q] = bok ? *(const float4*)(Bp + kt + q * 4) : z4;
        }
        if (kb) {
#pragma unroll
            for (int q = 0; q < 4; q++) {
                float4 u = *(const float4*)(kb + kt + akb + q * 4);
                av[q].x += u.x; av[q].y += u.y; av[q].z += u.z; av[q].w += u.w;
            }
        }
    };
    auto sts_chunk = [&](int buf) {
        uint32_t* Ah = S + buf * GB_SET_U32;
        uint32_t* Al = Ah + 2560;
        uint32_t* Bh = Al + 2560;
        uint32_t* Bl = Bh + 2560;
#pragma unroll
        for (int q = 0; q < 4; q++) {
            const int idx = arow * 20 + (akb + q * 4) / 2;
            uint2 hi, lo;
            split4(av[q], hi, lo);
            *(uint2*)&Ah[idx] = hi;
            if (use3) *(uint2*)&Al[idx] = lo;
            split4(bv[q], hi, lo);
            *(uint2*)&Bh[idx] = hi; *(uint2*)&Bl[idx] = lo;
        }
    };

    const int aRow = wm * 64 + ((lane >> 3) & 1) * 8 + (lane & 7);
    const uint32_t aOff = (uint32_t)(aRow * 80 + (lane >> 4) * 8 * 2);
    const int l16 = lane & 15;
    const uint32_t bOff =
        (uint32_t)((wn * 32 + (l16 & 7)) * 80 + ((l16 >> 3) & 1) * 8 * 2);

    const int nc = K >> 5;
    ldg_chunk(0);
    sts_chunk(0);
    if (nc > 1) ldg_chunk(32);
    __syncthreads();

    for (int c = 0; c < nc; c++) {
        if (c + 1 < nc) sts_chunk((c + 1) & 1);
        if (c + 2 < nc) ldg_chunk((c + 2) * 32);

        const uint32_t bufB = sB + (c & 1) * (GB_SET_U32 * 4);
        const uint32_t ahB = bufB, alB = bufB + 10240;
        const uint32_t bhB = bufB + 20480, blB = bufB + 30720;
#pragma unroll
        for (int kc = 0; kc < 32; kc += 16) {
            uint32_t bhf[4][2], blf[4][2];
#pragma unroll
            for (int nt = 0; nt < 4; nt++) {
                const uint32_t off = bOff + nt * 8 * 80 + kc * 2;
                ldsm2(bhf[nt], bhB + off);
                ldsm2(blf[nt], blB + off);
            }
#pragma unroll
            for (int mt = 0; mt < 4; mt++) {
                const uint32_t off = aOff + mt * 16 * 80 + kc * 2;
                uint32_t a_h[4], a_l[4];
                ldsm4(a_h, ahB + off);
#pragma unroll
                for (int nt = 0; nt < 4; nt++) mmab(acc[mt][nt], a_h, bhf[nt]);
#pragma unroll
                for (int nt = 0; nt < 4; nt++) mmab(acc[mt][nt], a_h, blf[nt]);
                if (use3) {
                    ldsm4(a_l, alB + off);
#pragma unroll
                    for (int nt = 0; nt < 4; nt++) mmab(acc[mt][nt], a_l, bhf[nt]);
                }
            }
        }
        __syncthreads();
    }

    const int g = lane >> 2, tc = (lane & 3) * 2;
#pragma unroll
    for (int mt = 0; mt < 4; mt++) {
        const int r = m0 + wm * 64 + mt * 16 + g;
#pragma unroll
        for (int nt = 0; nt < 4; nt++) {
            const int col = n0 + wn * 32 + nt * 8 + tc;
            float b0 = 0.f, b1 = 0.f;
            if (nbias) { b0 = nbias[col]; b1 = nbias[col + 1]; }
            const float* a4 = acc[mt][nt];
            if (r < M) {
                float* cp = Cz + (size_t)r * Cld + col;
                if (col + 1 < Ncap)
                    *(float2*)cp = make_float2(a4[0] + b0, a4[1] + b1);
                else if (col < Ncap)
                    cp[0] = a4[0] + b0;
            }
            if (r + 8 < M) {
                float* cp = Cz + (size_t)(r + 8) * Cld + col;
                if (col + 1 < Ncap)
                    *(float2*)cp = make_float2(a4[2] + b0, a4[3] + b1);
                else if (col < Ncap)
                    cp[0] = a4[2] + b0;
            }
        }
    }
}

// ---------------------------------------------------------------------------
// Merged projection kernel: z selects {Q, K, V, P}.
// ---------------------------------------------------------------------------
struct ProjArgs {
    const float* A[4];
    const float* W[4];
    const float* bias[4];
    float* C[4];
    int M[4];
    int use3[4];
};

__global__ __launch_bounds__(256, 2) void proj_kernel(ProjArgs pa)
{
    extern __shared__ uint32_t gsm[];
    const int z = blockIdx.z;
    const int M = pa.M[z];
    const int m0 = blockIdx.y * 128;
    if (m0 >= M) return;
    gemm_body(pa.A[z], pa.W[z], pa.bias[z], nullptr, pa.C[z],
              M, 512, 512, 512, 512, m0, blockIdx.x * 128, gsm,
              pa.use3[z] != 0);
}

// ---------------------------------------------------------------------------
// BD band GEMM: per (b,h)  (Q+v) P^T -> g_BD (ld 1024), band tiles only.
// ---------------------------------------------------------------------------
__global__ __launch_bounds__(256, 2) void bd_kernel(const float* __restrict__ pbv)
{
    extern __shared__ uint32_t gsm[];
    const int z = blockIdx.z;
    const int m0 = blockIdx.y * 128, n0 = blockIdx.x * 128;
    if (n0 > 1022 - m0 || n0 + 127 < 384 - m0) return;
    const int b = z >> 3, h = z & 7;
    const float* Az = g_Q + (size_t)b * (512 * 512) + h * 64;
    const float* Bz = g_P + (size_t)b * (NPOS * 512) + h * 64;
    float* Cz = g_BD + (size_t)z * (512 * BD_LD);
    gemm_body(Az, Bz, nullptr, pbv + h * 64, Cz,
              512, NPOS, 64, BD_LD, NPOS, m0, n0, gsm, true);
}

// ===========================================================================
// Flash attention v4: per (bh, i-tile 64), j-tile 64 (8 iters).
//   S = (Q+u)K^T (fp16 3-term) + BD band; online softmax;
//   O += P_fp16·Vh + P_fp16·Vl.
// smem 65.3KB -> 3 CTAs/SM; grid (1,8,128)=1024 blocks.
// ===========================================================================
#define FL_QH 0
#define FL_QL 9216
#define FL_KH 18432
#define FL_KL 27648
#define FL_VH 36864
#define FL_VL 46080
#define FL_PH 55296
#define FL_RED 64512
#define FL_SF  65536
#define FL_LB  65792
#define FL_SMEM 66816

__global__ __launch_bounds__(256, 3) void flash_kernel(const float* __restrict__ pbu)
{
    extern __shared__ char dsm[];
    uint32_t* QH = (uint32_t*)(dsm + FL_QH);   // 64 x 36 u32 (pitch 144B)
    uint32_t* QL = (uint32_t*)(dsm + FL_QL);
    uint32_t* KH = (uint32_t*)(dsm + FL_KH);   // 64 x 36 u32
    uint32_t* KL = (uint32_t*)(dsm + FL_KL);
    uint32_t* VH = (uint32_t*)(dsm + FL_VH);   // 64 x 36 u32
    uint32_t* VL = (uint32_t*)(dsm + FL_VL);
    uint32_t* PH = (uint32_t*)(dsm + FL_PH);   // 64 x 36 u32
    float* red  = (float*)(dsm + FL_RED);      // [4][64]
    float* sfb  = (float*)(dsm + FL_SF);       // [64]
    float* lbuf = (float*)(dsm + FL_LB);       // [4][64]

    const int tid = threadIdx.x, lane = tid & 31, wid = tid >> 5;
    const int wm = wid >> 2, wn = wid & 3;     // S: 2(m) x 4(n), warp 32x16
    const int wm2 = wid >> 1, wn2 = wid & 1;   // O: 4(m) x 2(d), warp 16x32
    const int it = blockIdx.y, z = blockIdx.z;
    const int b = z >> 3, h = z & 7;
    const int i0 = it * 64;

    const float* Qb = g_Q + ((size_t)b * 512) * 512 + h * 64;
    const float* Kb = g_K + ((size_t)b * 512) * 512 + h * 64;
    const float* Vb = g_V + ((size_t)b * 512) * 512 + h * 64;
    const float* BDb = g_BD + (size_t)z * (512 * BD_LD);

    // ---- load Q+u tile (64 x 64) into smem fp16 hi/lo ----
    {
        const int r = tid >> 2, c0 = (tid & 3) * 16;
        const float* qp = Qb + (size_t)(i0 + r) * 512 + c0;
        const float* up = pbu + h * 64 + c0;
#pragma unroll
        for (int q = 0; q < 4; q++) {
            float4 v = *(const float4*)(qp + q * 4);
            float4 u = *(const float4*)(up + q * 4);
            v.x += u.x; v.y += u.y; v.z += u.z; v.w += u.w;
            uint2 hi, lo;
            split4(v, hi, lo);
            const int idx = r * 36 + (c0 + q * 4) / 2;
            *(uint2*)&QH[idx] = hi; *(uint2*)&QL[idx] = lo;
        }
    }

    const uint32_t qhB = smem_u32(QH), qlB = smem_u32(QL);
    const uint32_t khB = smem_u32(KH), klB = smem_u32(KL);
    const uint32_t vhB = smem_u32(VH), vlB = smem_u32(VL);
    const uint32_t phB = smem_u32(PH);

    const int g = lane >> 2, tc = (lane & 3) * 2;
    const int l16 = lane & 15;
    const uint32_t aOff =
        (uint32_t)((wm * 32 + ((lane >> 3) & 1) * 8 + (lane & 7)) * 144 +
                   (lane >> 4) * 8 * 2);
    const uint32_t bOff =
        (uint32_t)((wn * 16 + (l16 & 7)) * 144 + ((l16 >> 3) & 1) * 8 * 2);
    const uint32_t pOff =
        (uint32_t)((wm2 * 16 + ((lane >> 3) & 1) * 8 + (lane & 7)) * 144 +
                   (lane >> 4) * 8 * 2);
    const int vR = ((l16 >> 3) & 1) * 8 + (l16 & 7);

    float m_loc[4], l_loc[4];
#pragma unroll
    for (int q = 0; q < 4; q++) { m_loc[q] = -1e30f; l_loc[q] = 0.f; }
    float oacc[4][4];
#pragma unroll
    for (int j = 0; j < 4; j++)
#pragma unroll
        for (int q = 0; q < 4; q++) oacc[j][q] = 0.f;

    for (int jt = 0; jt < 8; jt++) {
        const int j0 = jt * 64;
        const int r = tid >> 2, c0v = (tid & 3) * 16;
        float4 kreg[4], vreg[4];
#pragma unroll
        for (int q = 0; q < 4; q++) {
            kreg[q] = *(const float4*)(Kb + (size_t)(j0 + r) * 512 + c0v + q * 4);
            vreg[q] = *(const float4*)(Vb + (size_t)(j0 + r) * 512 + c0v + q * 4);
        }
        __syncthreads();   // prior O-MMA done with K/V/P buffers
#pragma unroll
        for (int q = 0; q < 4; q++) {
            uint2 hi, lo;
            const int idx = r * 36 + (c0v + q * 4) / 2;
            split4(kreg[q], hi, lo);
            *(uint2*)&KH[idx] = hi; *(uint2*)&KL[idx] = lo;
            split4(vreg[q], hi, lo);
            *(uint2*)&VH[idx] = hi; *(uint2*)&VL[idx] = lo;
        }
        __syncthreads();

        // ---- S = (Q+u) K^T via fp16 3-term MMA (64 x 64) ----
        float acc[2][2][4];
#pragma unroll
        for (int i = 0; i < 2; i++)
#pragma unroll
            for (int j = 0; j < 2; j++)
#pragma unroll
                for (int q = 0; q < 4; q++) acc[i][j][q] = 0.f;

#pragma unroll
        for (int kc = 0; kc < 64; kc += 16) {
            uint32_t bhf[2][2], blf[2][2];
#pragma unroll
            for (int nt = 0; nt < 2; nt++) {
                const uint32_t off = bOff + nt * 8 * 144 + kc * 2;
                ldsm2(bhf[nt], khB + off);
                ldsm2(blf[nt], klB + off);
            }
#pragma unroll
            for (int mt = 0; mt < 2; mt++) {
                const uint32_t off = aOff + mt * 16 * 144 + kc * 2;
                uint32_t a_h[4], a_l[4];
                ldsm4(a_h, qhB + off);
                ldsm4(a_l, qlB + off);
#pragma unroll
                for (int nt = 0; nt < 2; nt++) mmab(acc[mt][nt], a_h, bhf[nt]);
#pragma unroll
                for (int nt = 0; nt < 2; nt++) mmab(acc[mt][nt], a_h, blf[nt]);
#pragma unroll
                for (int nt = 0; nt < 2; nt++) mmab(acc[mt][nt], a_l, bhf[nt]);
            }
        }

        // ---- add BD band, scale, row max ----
        float pmax[4];
#pragma unroll
        for (int q = 0; q < 4; q++) pmax[q] = -1e30f;
#pragma unroll
        for (int mt = 0; mt < 2; mt++) {
            const int ilo = i0 + wm * 32 + mt * 16 + g;
            const int ihi = ilo + 8;
            const float* bdlo = BDb + (size_t)ilo * BD_LD + (511 - ilo);
            const float* bdhi = BDb + (size_t)ihi * BD_LD + (511 - ihi);
#pragma unroll
            for (int nt = 0; nt < 2; nt++) {
                const int col = j0 + wn * 16 + nt * 8 + tc;
                float* a4 = acc[mt][nt];
                a4[0] = (a4[0] + bdlo[col]) * 0.125f;
                a4[1] = (a4[1] + bdlo[col + 1]) * 0.125f;
                a4[2] = (a4[2] + bdhi[col]) * 0.125f;
                a4[3] = (a4[3] + bdhi[col + 1]) * 0.125f;
                pmax[2 * mt]     = fmaxf(pmax[2 * mt], fmaxf(a4[0], a4[1]));
                pmax[2 * mt + 1] = fmaxf(pmax[2 * mt + 1], fmaxf(a4[2], a4[3]));
            }
        }
#pragma unroll
        for (int q = 0; q < 4; q++) {
            pmax[q] = fmaxf(pmax[q], __shfl_xor_sync(0xffffffffu, pmax[q], 1));
            pmax[q] = fmaxf(pmax[q], __shfl_xor_sync(0xffffffffu, pmax[q], 2));
        }
        if ((lane & 3) == 0) {
#pragma unroll
            for (int mt = 0; mt < 2; mt++) {
                const int rl = wm * 32 + mt * 16 + g;
                red[wn * 64 + rl] = pmax[2 * mt];
                red[wn * 64 + rl + 8] = pmax[2 * mt + 1];
            }
        }
        __syncthreads();

        // ---- global row max, rescale factors ----
#pragma unroll
        for (int mt = 0; mt < 2; mt++) {
#pragma unroll
            for (int hf = 0; hf < 2; hf++) {
                const int rl = wm * 32 + mt * 16 + g + hf * 8;
                const int q = 2 * mt + hf;
                float tm = fmaxf(fmaxf(red[rl], red[64 + rl]),
                                 fmaxf(red[128 + rl], red[192 + rl]));
                float mn = fmaxf(m_loc[q], tm);
                float sf = __expf(m_loc[q] - mn);
                l_loc[q] *= sf;
                m_loc[q] = mn;
                if (wn == 0 && (lane & 3) == 0) sfb[rl] = sf;
            }
        }

        // ---- exp, accumulate l, store P (fp16 single) ----
#pragma unroll
        for (int mt = 0; mt < 2; mt++) {
            const int rlo = wm * 32 + mt * 16 + g;
            const float mlo = m_loc[2 * mt], mhi = m_loc[2 * mt + 1];
#pragma unroll
            for (int nt = 0; nt < 2; nt++) {
                const int col = wn * 16 + nt * 8 + tc;
                float* a4 = acc[mt][nt];
                float p0 = __expf(a4[0] - mlo);
                float p1 = __expf(a4[1] - mlo);
                float p2 = __expf(a4[2] - mhi);
                float p3 = __expf(a4[3] - mhi);
                l_loc[2 * mt] += p0 + p1;
                l_loc[2 * mt + 1] += p2 + p3;
                PH[rlo * 36 + col / 2] =
                    pkhf(__float2half_rn(p0), __float2half_rn(p1));
                PH[(rlo + 8) * 36 + col / 2] =
                    pkhf(__float2half_rn(p2), __float2half_rn(p3));
            }
        }
        __syncthreads();   // P + sfb ready

        // ---- O rescale + O += P·Vh + P·Vl ----
        {
            const int r2 = wm2 * 16 + g;
            const float slo = sfb[r2], shi = sfb[r2 + 8];
#pragma unroll
            for (int nt2 = 0; nt2 < 4; nt2++) {
                oacc[nt2][0] *= slo;
                oacc[nt2][1] *= slo;
                oacc[nt2][2] *= shi;
                oacc[nt2][3] *= shi;
            }
        }
#pragma unroll
        for (int kc = 0; kc < 4; kc++) {
            uint32_t bhf[4][2], blf[4][2];
#pragma unroll
            for (int nt2 = 0; nt2 < 4; nt2++) {
                const uint32_t off =
                    (uint32_t)((kc * 16 + vR) * 144 + (wn2 * 32 + nt2 * 8) * 2);
                ldsm2t(bhf[nt2], vhB + off);
                ldsm2t(blf[nt2], vlB + off);
            }
            {
                const uint32_t off = pOff + kc * 32;
                uint32_t a_h[4];
                ldsm4(a_h, phB + off);
#pragma unroll
                for (int nt2 = 0; nt2 < 4; nt2++) mmab(oacc[nt2], a_h, bhf[nt2]);
#pragma unroll
                for (int nt2 = 0; nt2 < 4; nt2++) mmab(oacc[nt2], a_h, blf[nt2]);
            }
        }
    }

    // ---- final l reduction + normalize + store ----
#pragma unroll
    for (int q = 0; q < 4; q++) {
        l_loc[q] += __shfl_xor_sync(0xffffffffu, l_loc[q], 1);
        l_loc[q] += __shfl_xor_sync(0xffffffffu, l_loc[q], 2);
    }
    if ((lane & 3) == 0) {
#pragma unroll
        for (int mt = 0; mt < 2; mt++) {
            const int rl = wm * 32 + mt * 16 + g;
            lbuf[wn * 64 + rl] = l_loc[2 * mt];
            lbuf[wn * 64 + rl + 8] = l_loc[2 * mt + 1];
        }
    }
    __syncthreads();

    float* Cb = g_C + ((size_t)b * 512 + i0) * 512 + h * 64;
    {
        const int r2 = wm2 * 16 + g;
        const float llo = lbuf[r2] + lbuf[64 + r2] + lbuf[128 + r2] + lbuf[192 + r2];
        const float lhi = lbuf[r2 + 8] + lbuf[64 + r2 + 8] + lbuf[128 + r2 + 8] +
                          lbuf[192 + r2 + 8];
        const float ilo = 1.0f / llo, ihi = 1.0f / lhi;
#pragma unroll
        for (int nt2 = 0; nt2 < 4; nt2++) {
            const int col = wn2 * 32 + nt2 * 8 + tc;
            const float* a4 = oacc[nt2];
            *(float2*)(Cb + (size_t)r2 * 512 + col) =
                make_float2(a4[0] * ilo, a4[1] * ilo);
            *(float2*)(Cb + (size_t)(r2 + 8) * 512 + col) =
                make_float2(a4[2] * ihi, a4[3] * ihi);
        }
    }
}

// ---------------------------------------------------------------------------
extern "C" void kernel_launch(void* const* d_in, const int* in_sizes, int n_in,
                              void* d_out, int out_size)
{
    const float* query = (const float*)d_in[0];
    const float* key   = (const float*)d_in[1];
    const float* value = (const float*)d_in[2];
    const float* pos   = (const float*)d_in[3];
    const float* Wq  = (const float*)d_in[6];
    const float* bq  = (const float*)d_in[7];
    const float* Wk  = (const float*)d_in[8];
    const float* bk  = (const float*)d_in[9];
    const float* Wv  = (const float*)d_in[10];
    const float* bv  = (const float*)d_in[11];
    const float* Wp  = (const float*)d_in[12];
    const float* Wo  = (const float*)d_in[13];
    const float* bo  = (const float*)d_in[14];
    const float* pbu = (const float*)d_in[15];
    const float* pbv = (const float*)d_in[16];

    void *pQ, *pK, *pV, *pP, *pC;
    cudaGetSymbolAddress(&pQ, g_Q);
    cudaGetSymbolAddress(&pK, g_K);
    cudaGetSymbolAddress(&pV, g_V);
    cudaGetSymbolAddress(&pP, g_P);
    cudaGetSymbolAddress(&pC, g_C);

    cudaFuncSetAttribute(flash_kernel,
                         cudaFuncAttributeMaxDynamicSharedMemorySize, FL_SMEM);
    cudaFuncSetAttribute(proj_kernel,
                         cudaFuncAttributeMaxDynamicSharedMemorySize, GB_SMEM);
    cudaFuncSetAttribute(bd_kernel,
                         cudaFuncAttributeMaxDynamicSharedMemorySize, GB_SMEM);

    const int Mq = BB * T1;     // 8192
    const int Mp = BB * NPOS;   // 16368

    ProjArgs pa;
    pa.A[0] = query; pa.W[0] = Wq; pa.bias[0] = bq;      pa.C[0] = (float*)pQ; pa.M[0] = Mq; pa.use3[0] = 1;
    pa.A[1] = key;   pa.W[1] = Wk; pa.bias[1] = bk;      pa.C[1] = (float*)pK; pa.M[1] = Mq; pa.use3[1] = 1;
    pa.A[2] = value; pa.W[2] = Wv; pa.bias[2] = bv;      pa.C[2] = (float*)pV; pa.M[2] = Mq; pa.use3[2] = 0;
    pa.A[3] = pos;   pa.W[3] = Wp; pa.bias[3] = nullptr; pa.C[3] = (float*)pP; pa.M[3] = Mp; pa.use3[3] = 1;
    proj_kernel<<<dim3(4, 128, 4), 256, GB_SMEM>>>(pa);

    bd_kernel<<<dim3(8, 4, BB * NH), 256, GB_SMEM>>>(pbv);

    flash_kernel<<<dim3(1, 8, BB * NH), 256, FL_SMEM>>>(pbu);

    ProjArgs po;
    for (int i = 0; i < 4; i++) {
        po.A[i] = (const float*)pC; po.W[i] = Wo; po.bias[i] = bo;
        po.C[i] = (float*)d_out; po.M[i] = Mq; po.use3[i] = 0;
    }
    proj_kernel<<<dim3(4, 64, 1), 256, GB_SMEM>>>(po);
}

// round 17
// speedup vs baseline: 1.0511x; 1.0511x over previous
#include <cuda_runtime.h>
#include <cuda_fp16.h>
#include <cstdint>
#include <cstddef>

#define BB   16
#define T1   512
#define NH   8
#define DK   64
#define EMB  512
#define NPOS 1023
#define BD_LD 1024

// ---------------- scratch (module globals; no runtime allocation) ----------
__device__ float g_Q[BB * T1 * EMB];
__device__ float g_K[BB * T1 * EMB];
__device__ float g_V[BB * T1 * EMB];
__device__ float g_P[BB * NPOS * EMB];
__device__ float g_BD[(size_t)BB * NH * T1 * BD_LD];
__device__ float g_C[BB * T1 * EMB];

// ======================= helpers ===========================================
__device__ __forceinline__ uint32_t smem_u32(const void* p) {
    uint32_t a;
    asm("{ .reg .u64 t; cvta.to.shared.u64 t, %1; cvt.u32.u64 %0, t; }"
        : "=r"(a) : "l"(p));
    return a;
}
__device__ __forceinline__ uint32_t pkhf(__half a, __half b) {
    __half2 t;
    t.x = a; t.y = b;
    return *reinterpret_cast<uint32_t*>(&t);
}
// fp16 hi/lo split: a = hi + lo. hi*hi products exact in fp32 accum.
__device__ __forceinline__ void split4(float4 v, uint2& hi, uint2& lo) {
    __half hx = __float2half_rn(v.x);
    __half hy = __float2half_rn(v.y);
    __half hz = __float2half_rn(v.z);
    __half hw = __float2half_rn(v.w);
    float rx = v.x - __half2float(hx);
    float ry = v.y - __half2float(hy);
    float rz = v.z - __half2float(hz);
    float rw = v.w - __half2float(hw);
    hi = make_uint2(pkhf(hx, hy), pkhf(hz, hw));
    lo = make_uint2(pkhf(__float2half_rn(rx), __float2half_rn(ry)),
                    pkhf(__float2half_rn(rz), __float2half_rn(rw)));
}
__device__ __forceinline__ void ldsm4(uint32_t* r, uint32_t a) {
    asm volatile("ldmatrix.sync.aligned.m8n8.x4.shared.b16 {%0,%1,%2,%3}, [%4];"
                 : "=r"(r[0]), "=r"(r[1]), "=r"(r[2]), "=r"(r[3]) : "r"(a));
}
__device__ __forceinline__ void ldsm2(uint32_t* r, uint32_t a) {
    asm volatile("ldmatrix.sync.aligned.m8n8.x2.shared.b16 {%0,%1}, [%2];"
                 : "=r"(r[0]), "=r"(r[1]) : "r"(a));
}
__device__ __forceinline__ void ldsm2t(uint32_t* r, uint32_t a) {
    asm volatile("ldmatrix.sync.aligned.m8n8.x2.trans.shared.b16 {%0,%1}, [%2];"
                 : "=r"(r[0]), "=r"(r[1]) : "r"(a));
}
__device__ __forceinline__ void mmab(float* c, const uint32_t* a, const uint32_t* b) {
    asm volatile("mma.sync.aligned.m16n8k16.row.col.f32.f16.f16.f32 "
                 "{%0,%1,%2,%3}, {%4,%5,%6,%7}, {%8,%9}, {%0,%1,%2,%3};"
                 : "+f"(c[0]), "+f"(c[1]), "+f"(c[2]), "+f"(c[3])
                 : "r"(a[0]), "r"(a[1]), "r"(a[2]), "r"(a[3]),
                   "r"(b[0]), "r"(b[1]));
}

// ===========================================================================
// Double-buffered GEMM body (fp16 split): C = A B^T (+nbias) (+kbias on A)
// 128x128 tile, BK=32, 8 warps (2x4). use3: 3-term vs 2-term.
// ===========================================================================
#define GB_SET_U32 10240
#define GB_SMEM (2 * GB_SET_U32 * 4)

__device__ __forceinline__ void gemm_body(
    const float* __restrict__ Az, const float* __restrict__ Bz,
    const float* __restrict__ nbias, const float* __restrict__ kb,
    float* __restrict__ Cz, int M, int Brows, int K, int Cld, int Ncap,
    int m0, int n0, uint32_t* S, bool use3)
{
    const int tid = threadIdx.x;
    const int lane = tid & 31, wid = tid >> 5;
    const int wm = wid >> 2, wn = wid & 3;

    const int arow = tid >> 1;
    const int akb  = (tid & 1) * 16;
    const bool aok = (m0 + arow) < M;
    const bool bok = (n0 + arow) < Brows;
    const float* Ap = Az + (size_t)(m0 + arow) * 512 + akb;
    const float* Bp = Bz + (size_t)(n0 + arow) * 512 + akb;

    float acc[4][4][4];
#pragma unroll
    for (int i = 0; i < 4; i++)
#pragma unroll
        for (int j = 0; j < 4; j++)
#pragma unroll
            for (int q = 0; q < 4; q++) acc[i][j][q] = 0.f;

    const uint32_t sB = smem_u32(S);
    const float4 z4 = make_float4(0.f, 0.f, 0.f, 0.f);
    float4 av[4], bv[4];

    auto ldg_chunk = [&](int kt) {
#pragma unroll
        for (int q = 0; q < 4; q++) {
            av[q] = aok ? *(const float4*)(Ap + kt + q * 4) : z4;
            bv[q] = bok ? *(const float4*)(Bp + kt + q * 4) : z4;
        }
        if (kb) {
#pragma unroll
            for (int q = 0; q < 4; q++) {
                float4 u = *(const float4*)(kb + kt + akb + q * 4);
                av[q].x += u.x; av[q].y += u.y; av[q].z += u.z; av[q].w += u.w;
            }
        }
    };
    auto sts_chunk = [&](int buf) {
        uint32_t* Ah = S + buf * GB_SET_U32;
        uint32_t* Al = Ah + 2560;
        uint32_t* Bh = Al + 2560;
        uint32_t* Bl = Bh + 2560;
#pragma unroll
        for (int q = 0; q < 4; q++) {
            const int idx = arow * 20 + (akb + q * 4) / 2;
            uint2 hi, lo;
            split4(av[q], hi, lo);
            *(uint2*)&Ah[idx] = hi;
            if (use3) *(uint2*)&Al[idx] = lo;
            split4(bv[q], hi, lo);
            *(uint2*)&Bh[idx] = hi; *(uint2*)&Bl[idx] = lo;
        }
    };

    const int aRow = wm * 64 + ((lane >> 3) & 1) * 8 + (lane & 7);
    const uint32_t aOff = (uint32_t)(aRow * 80 + (lane >> 4) * 8 * 2);
    const int l16 = lane & 15;
    const uint32_t bOff =
        (uint32_t)((wn * 32 + (l16 & 7)) * 80 + ((l16 >> 3) & 1) * 8 * 2);

    const int nc = K >> 5;
    ldg_chunk(0);
    sts_chunk(0);
    if (nc > 1) ldg_chunk(32);
    __syncthreads();

    for (int c = 0; c < nc; c++) {
        if (c + 1 < nc) sts_chunk((c + 1) & 1);
        if (c + 2 < nc) ldg_chunk((c + 2) * 32);

        const uint32_t bufB = sB + (c & 1) * (GB_SET_U32 * 4);
        const uint32_t ahB = bufB, alB = bufB + 10240;
        const uint32_t bhB = bufB + 20480, blB = bufB + 30720;
#pragma unroll
        for (int kc = 0; kc < 32; kc += 16) {
            uint32_t bhf[4][2], blf[4][2];
#pragma unroll
            for (int nt = 0; nt < 4; nt++) {
                const uint32_t off = bOff + nt * 8 * 80 + kc * 2;
                ldsm2(bhf[nt], bhB + off);
                ldsm2(blf[nt], blB + off);
            }
#pragma unroll
            for (int mt = 0; mt < 4; mt++) {
                const uint32_t off = aOff + mt * 16 * 80 + kc * 2;
                uint32_t a_h[4], a_l[4];
                ldsm4(a_h, ahB + off);
#pragma unroll
                for (int nt = 0; nt < 4; nt++) mmab(acc[mt][nt], a_h, bhf[nt]);
#pragma unroll
                for (int nt = 0; nt < 4; nt++) mmab(acc[mt][nt], a_h, blf[nt]);
                if (use3) {
                    ldsm4(a_l, alB + off);
#pragma unroll
                    for (int nt = 0; nt < 4; nt++) mmab(acc[mt][nt], a_l, bhf[nt]);
                }
            }
        }
        __syncthreads();
    }

    const int g = lane >> 2, tc = (lane & 3) * 2;
#pragma unroll
    for (int mt = 0; mt < 4; mt++) {
        const int r = m0 + wm * 64 + mt * 16 + g;
#pragma unroll
        for (int nt = 0; nt < 4; nt++) {
            const int col = n0 + wn * 32 + nt * 8 + tc;
            float b0 = 0.f, b1 = 0.f;
            if (nbias) { b0 = nbias[col]; b1 = nbias[col + 1]; }
            const float* a4 = acc[mt][nt];
            if (r < M) {
                float* cp = Cz + (size_t)r * Cld + col;
                if (col + 1 < Ncap)
                    *(float2*)cp = make_float2(a4[0] + b0, a4[1] + b1);
                else if (col < Ncap)
                    cp[0] = a4[0] + b0;
            }
            if (r + 8 < M) {
                float* cp = Cz + (size_t)(r + 8) * Cld + col;
                if (col + 1 < Ncap)
                    *(float2*)cp = make_float2(a4[2] + b0, a4[3] + b1);
                else if (col < Ncap)
                    cp[0] = a4[2] + b0;
            }
        }
    }
}

// ---------------------------------------------------------------------------
// Merged projection kernel: z selects {Q, K, V, P}.
// ---------------------------------------------------------------------------
struct ProjArgs {
    const float* A[4];
    const float* W[4];
    const float* bias[4];
    float* C[4];
    int M[4];
    int use3[4];
};

__global__ __launch_bounds__(256, 2) void proj_kernel(ProjArgs pa)
{
    extern __shared__ uint32_t gsm[];
    const int z = blockIdx.z;
    const int M = pa.M[z];
    const int m0 = blockIdx.y * 128;
    if (m0 >= M) return;
    gemm_body(pa.A[z], pa.W[z], pa.bias[z], nullptr, pa.C[z],
              M, 512, 512, 512, 512, m0, blockIdx.x * 128, gsm,
              pa.use3[z] != 0);
}

// ---------------------------------------------------------------------------
// BD band GEMM: per (b,h)  (Q+v) P^T -> g_BD (ld 1024), band tiles only.
// ---------------------------------------------------------------------------
__global__ __launch_bounds__(256, 2) void bd_kernel(const float* __restrict__ pbv)
{
    extern __shared__ uint32_t gsm[];
    const int z = blockIdx.z;
    const int m0 = blockIdx.y * 128, n0 = blockIdx.x * 128;
    if (n0 > 1022 - m0 || n0 + 127 < 384 - m0) return;
    const int b = z >> 3, h = z & 7;
    const float* Az = g_Q + (size_t)b * (512 * 512) + h * 64;
    const float* Bz = g_P + (size_t)b * (NPOS * 512) + h * 64;
    float* Cz = g_BD + (size_t)z * (512 * BD_LD);
    gemm_body(Az, Bz, nullptr, pbv + h * 64, Cz,
              512, NPOS, 64, BD_LD, NPOS, m0, n0, gsm, true);
}

// ===========================================================================
// Flash attention (R15 shape): per (bh, i-tile 128), j-tile 64 (8 iters).
//   S = (Q+u)K^T (fp16 3-term) + BD band; online softmax;
//   O += P_fp16·Vh + P_fp16·Vl.
// BD band loads hoisted before S-MMA so their L2 latency overlaps MMAs.
// smem 96.75KB -> 2 CTAs/SM.
// ===========================================================================
#define FL_QH 0
#define FL_QL 18432
#define FL_KH 36864
#define FL_KL 46080
#define FL_VH 55296
#define FL_VL 64512
#define FL_PH 73728
#define FL_RED 92160
#define FL_SF  94208
#define FL_LB  94720
#define FL_SMEM 96768

__global__ __launch_bounds__(256, 2) void flash_kernel(const float* __restrict__ pbu)
{
    extern __shared__ char dsm[];
    uint32_t* QH = (uint32_t*)(dsm + FL_QH);   // 128 x 36 u32 (pitch 144B)
    uint32_t* QL = (uint32_t*)(dsm + FL_QL);
    uint32_t* KH = (uint32_t*)(dsm + FL_KH);   // 64 x 36 u32
    uint32_t* KL = (uint32_t*)(dsm + FL_KL);
    uint32_t* VH = (uint32_t*)(dsm + FL_VH);   // 64 x 36 u32
    uint32_t* VL = (uint32_t*)(dsm + FL_VL);
    uint32_t* PH = (uint32_t*)(dsm + FL_PH);   // 128 x 36 u32
    float* red  = (float*)(dsm + FL_RED);      // [4][128]
    float* sfb  = (float*)(dsm + FL_SF);       // [128]
    float* lbuf = (float*)(dsm + FL_LB);       // [4][128]

    const int tid = threadIdx.x, lane = tid & 31, wid = tid >> 5;
    const int wm = wid >> 2, wn = wid & 3;     // S phase: 2(m) x 4(n)
    const int wm2 = wid >> 1, wn2 = wid & 1;   // O phase: 4(m) x 2(d)
    const int it = blockIdx.y, z = blockIdx.z;
    const int b = z >> 3, h = z & 7;
    const int i0 = it * 128;

    const float* Qb = g_Q + ((size_t)b * 512) * 512 + h * 64;
    const float* Kb = g_K + ((size_t)b * 512) * 512 + h * 64;
    const float* Vb = g_V + ((size_t)b * 512) * 512 + h * 64;
    const float* BDb = g_BD + (size_t)z * (512 * BD_LD);

    // ---- load Q+u tile (128 x 64) into smem fp16 hi/lo ----
    {
        const int r = tid >> 1, c0 = (tid & 1) * 32;
        const float* qp = Qb + (size_t)(i0 + r) * 512 + c0;
        const float* up = pbu + h * 64 + c0;
#pragma unroll
        for (int q = 0; q < 8; q++) {
            float4 v = *(const float4*)(qp + q * 4);
            float4 u = *(const float4*)(up + q * 4);
            v.x += u.x; v.y += u.y; v.z += u.z; v.w += u.w;
            uint2 hi, lo;
            split4(v, hi, lo);
            const int idx = r * 36 + (c0 + q * 4) / 2;
            *(uint2*)&QH[idx] = hi; *(uint2*)&QL[idx] = lo;
        }
    }

    const uint32_t qhB = smem_u32(QH), qlB = smem_u32(QL);
    const uint32_t khB = smem_u32(KH), klB = smem_u32(KL);
    const uint32_t vhB = smem_u32(VH), vlB = smem_u32(VL);
    const uint32_t phB = smem_u32(PH);

    const int g = lane >> 2, tc = (lane & 3) * 2;
    const int l16 = lane & 15;
    const uint32_t aOff =
        (uint32_t)((wm * 64 + ((lane >> 3) & 1) * 8 + (lane & 7)) * 144 +
                   (lane >> 4) * 8 * 2);
    const uint32_t bOff =
        (uint32_t)((wn * 16 + (l16 & 7)) * 144 + ((l16 >> 3) & 1) * 8 * 2);
    const uint32_t pOff =
        (uint32_t)((wm2 * 32 + ((lane >> 3) & 1) * 8 + (lane & 7)) * 144 +
                   (lane >> 4) * 8 * 2);
    const int vR = ((l16 >> 3) & 1) * 8 + (l16 & 7);

    float m_loc[8], l_loc[8];
#pragma unroll
    for (int q = 0; q < 8; q++) { m_loc[q] = -1e30f; l_loc[q] = 0.f; }
    float oacc[2][4][4];
#pragma unroll
    for (int i = 0; i < 2; i++)
#pragma unroll
        for (int j = 0; j < 4; j++)
#pragma unroll
            for (int q = 0; q < 4; q++) oacc[i][j][q] = 0.f;

    for (int jt = 0; jt < 8; jt++) {
        const int j0 = jt * 64;
        const int r = tid >> 2, c0v = (tid & 3) * 16;
        float4 kreg[4], vreg[4];
#pragma unroll
        for (int q = 0; q < 4; q++) {
            kreg[q] = *(const float4*)(Kb + (size_t)(j0 + r) * 512 + c0v + q * 4);
            vreg[q] = *(const float4*)(Vb + (size_t)(j0 + r) * 512 + c0v + q * 4);
        }
        __syncthreads();   // prior O-MMA done with K/V/P buffers
#pragma unroll
        for (int q = 0; q < 4; q++) {
            uint2 hi, lo;
            const int idx = r * 36 + (c0v + q * 4) / 2;
            split4(kreg[q], hi, lo);
            *(uint2*)&KH[idx] = hi; *(uint2*)&KL[idx] = lo;
            split4(vreg[q], hi, lo);
            *(uint2*)&VH[idx] = hi; *(uint2*)&VL[idx] = lo;
        }
        __syncthreads();

        // ---- hoisted BD band loads (overlap with S-MMA below) ----
        float bdv[4][2][4];
#pragma unroll
        for (int mt = 0; mt < 4; mt++) {
            const int ilo = i0 + wm * 64 + mt * 16 + g;
            const int ihi = ilo + 8;
            const float* bdlo = BDb + (size_t)ilo * BD_LD + (511 - ilo);
            const float* bdhi = BDb + (size_t)ihi * BD_LD + (511 - ihi);
#pragma unroll
            for (int nt = 0; nt < 2; nt++) {
                const int col = j0 + wn * 16 + nt * 8 + tc;
                bdv[mt][nt][0] = bdlo[col];
                bdv[mt][nt][1] = bdlo[col + 1];
                bdv[mt][nt][2] = bdhi[col];
                bdv[mt][nt][3] = bdhi[col + 1];
            }
        }

        // ---- S = (Q+u) K^T via fp16 3-term MMA (128 x 64) ----
        float acc[4][2][4];
#pragma unroll
        for (int i = 0; i < 4; i++)
#pragma unroll
            for (int j = 0; j < 2; j++)
#pragma unroll
                for (int q = 0; q < 4; q++) acc[i][j][q] = 0.f;

#pragma unroll
        for (int kc = 0; kc < 64; kc += 16) {
            uint32_t bhf[2][2], blf[2][2];
#pragma unroll
            for (int nt = 0; nt < 2; nt++) {
                const uint32_t off = bOff + nt * 8 * 144 + kc * 2;
                ldsm2(bhf[nt], khB + off);
                ldsm2(blf[nt], klB + off);
            }
#pragma unroll
            for (int mt = 0; mt < 4; mt++) {
                const uint32_t off = aOff + mt * 16 * 144 + kc * 2;
                uint32_t a_h[4], a_l[4];
                ldsm4(a_h, qhB + off);
                ldsm4(a_l, qlB + off);
#pragma unroll
                for (int nt = 0; nt < 2; nt++) mmab(acc[mt][nt], a_h, bhf[nt]);
#pragma unroll
                for (int nt = 0; nt < 2; nt++) mmab(acc[mt][nt], a_h, blf[nt]);
#pragma unroll
                for (int nt = 0; nt < 2; nt++) mmab(acc[mt][nt], a_l, bhf[nt]);
            }
        }

        // ---- add BD band (prefetched), scale, row max ----
        float pmax[8];
#pragma unroll
        for (int q = 0; q < 8; q++) pmax[q] = -1e30f;
#pragma unroll
        for (int mt = 0; mt < 4; mt++) {
#pragma unroll
            for (int nt = 0; nt < 2; nt++) {
                float* a4 = acc[mt][nt];
                const float* b4 = bdv[mt][nt];
                a4[0] = (a4[0] + b4[0]) * 0.125f;
                a4[1] = (a4[1] + b4[1]) * 0.125f;
                a4[2] = (a4[2] + b4[2]) * 0.125f;
                a4[3] = (a4[3] + b4[3]) * 0.125f;
                pmax[2 * mt]     = fmaxf(pmax[2 * mt], fmaxf(a4[0], a4[1]));
                pmax[2 * mt + 1] = fmaxf(pmax[2 * mt + 1], fmaxf(a4[2], a4[3]));
            }
        }
#pragma unroll
        for (int q = 0; q < 8; q++) {
            pmax[q] = fmaxf(pmax[q], __shfl_xor_sync(0xffffffffu, pmax[q], 1));
            pmax[q] = fmaxf(pmax[q], __shfl_xor_sync(0xffffffffu, pmax[q], 2));
        }
        if ((lane & 3) == 0) {
#pragma unroll
            for (int mt = 0; mt < 4; mt++) {
                const int rl = wm * 64 + mt * 16 + g;
                red[wn * 128 + rl] = pmax[2 * mt];
                red[wn * 128 + rl + 8] = pmax[2 * mt + 1];
            }
        }
        __syncthreads();

        // ---- global row max, rescale factors ----
#pragma unroll
        for (int mt = 0; mt < 4; mt++) {
#pragma unroll
            for (int hf = 0; hf < 2; hf++) {
                const int rl = wm * 64 + mt * 16 + g + hf * 8;
                const int q = 2 * mt + hf;
                float tm = fmaxf(fmaxf(red[rl], red[128 + rl]),
                                 fmaxf(red[256 + rl], red[384 + rl]));
                float mn = fmaxf(m_loc[q], tm);
                float sf = __expf(m_loc[q] - mn);
                l_loc[q] *= sf;
                m_loc[q] = mn;
                if (wn == 0 && (lane & 3) == 0) sfb[rl] = sf;
            }
        }

        // ---- exp, accumulate l, store P (fp16 single) ----
#pragma unroll
        for (int mt = 0; mt < 4; mt++) {
            const int rlo = wm * 64 + mt * 16 + g;
            const float mlo = m_loc[2 * mt], mhi = m_loc[2 * mt + 1];
#pragma unroll
            for (int nt = 0; nt < 2; nt++) {
                const int col = wn * 16 + nt * 8 + tc;
                float* a4 = acc[mt][nt];
                float p0 = __expf(a4[0] - mlo);
                float p1 = __expf(a4[1] - mlo);
                float p2 = __expf(a4[2] - mhi);
                float p3 = __expf(a4[3] - mhi);
                l_loc[2 * mt] += p0 + p1;
                l_loc[2 * mt + 1] += p2 + p3;
                PH[rlo * 36 + col / 2] =
                    pkhf(__float2half_rn(p0), __float2half_rn(p1));
                PH[(rlo + 8) * 36 + col / 2] =
                    pkhf(__float2half_rn(p2), __float2half_rn(p3));
            }
        }
        __syncthreads();   // P + sfb ready

        // ---- O rescale + O += P·Vh + P·Vl ----
#pragma unroll
        for (int mt2 = 0; mt2 < 2; mt2++) {
            const int r2 = wm2 * 32 + mt2 * 16 + g;
            const float slo = sfb[r2], shi = sfb[r2 + 8];
#pragma unroll
            for (int nt2 = 0; nt2 < 4; nt2++) {
                oacc[mt2][nt2][0] *= slo;
                oacc[mt2][nt2][1] *= slo;
                oacc[mt2][nt2][2] *= shi;
                oacc[mt2][nt2][3] *= shi;
            }
        }
#pragma unroll
        for (int kc = 0; kc < 4; kc++) {
            uint32_t bhf[4][2], blf[4][2];
#pragma unroll
            for (int nt2 = 0; nt2 < 4; nt2++) {
                const uint32_t off =
                    (uint32_t)((kc * 16 + vR) * 144 + (wn2 * 32 + nt2 * 8) * 2);
                ldsm2t(bhf[nt2], vhB + off);
                ldsm2t(blf[nt2], vlB + off);
            }
#pragma unroll
            for (int mt2 = 0; mt2 < 2; mt2++) {
                const uint32_t off = pOff + mt2 * 16 * 144 + kc * 32;
                uint32_t a_h[4];
                ldsm4(a_h, phB + off);
#pragma unroll
                for (int nt2 = 0; nt2 < 4; nt2++) mmab(oacc[mt2][nt2], a_h, bhf[nt2]);
#pragma unroll
                for (int nt2 = 0; nt2 < 4; nt2++) mmab(oacc[mt2][nt2], a_h, blf[nt2]);
            }
        }
    }

    // ---- final l reduction + normalize + store ----
#pragma unroll
    for (int q = 0; q < 8; q++) {
        l_loc[q] += __shfl_xor_sync(0xffffffffu, l_loc[q], 1);
        l_loc[q] += __shfl_xor_sync(0xffffffffu, l_loc[q], 2);
    }
    if ((lane & 3) == 0) {
#pragma unroll
        for (int mt = 0; mt < 4; mt++) {
            const int rl = wm * 64 + mt * 16 + g;
            lbuf[wn * 128 + rl] = l_loc[2 * mt];
            lbuf[wn * 128 + rl + 8] = l_loc[2 * mt + 1];
        }
    }
    __syncthreads();

    float* Cb = g_C + ((size_t)b * 512 + i0) * 512 + h * 64;
#pragma unroll
    for (int mt2 = 0; mt2 < 2; mt2++) {
        const int r2 = wm2 * 32 + mt2 * 16 + g;
        const float llo = lbuf[r2] + lbuf[128 + r2] + lbuf[256 + r2] + lbuf[384 + r2];
        const float lhi = lbuf[r2 + 8] + lbuf[128 + r2 + 8] + lbuf[256 + r2 + 8] +
                          lbuf[384 + r2 + 8];
        const float ilo = 1.0f / llo, ihi = 1.0f / lhi;
#pragma unroll
        for (int nt2 = 0; nt2 < 4; nt2++) {
            const int col = wn2 * 32 + nt2 * 8 + tc;
            const float* a4 = oacc[mt2][nt2];
            *(float2*)(Cb + (size_t)r2 * 512 + col) =
                make_float2(a4[0] * ilo, a4[1] * ilo);
            *(float2*)(Cb + (size_t)(r2 + 8) * 512 + col) =
                make_float2(a4[2] * ihi, a4[3] * ihi);
        }
    }
}

// ---------------------------------------------------------------------------
extern "C" void kernel_launch(void* const* d_in, const int* in_sizes, int n_in,
                              void* d_out, int out_size)
{
    const float* query = (const float*)d_in[0];
    const float* key   = (const float*)d_in[1];
    const float* value = (const float*)d_in[2];
    const float* pos   = (const float*)d_in[3];
    const float* Wq  = (const float*)d_in[6];
    const float* bq  = (const float*)d_in[7];
    const float* Wk  = (const float*)d_in[8];
    const float* bk  = (const float*)d_in[9];
    const float* Wv  = (const float*)d_in[10];
    const float* bv  = (const float*)d_in[11];
    const float* Wp  = (const float*)d_in[12];
    const float* Wo  = (const float*)d_in[13];
    const float* bo  = (const float*)d_in[14];
    const float* pbu = (const float*)d_in[15];
    const float* pbv = (const float*)d_in[16];

    void *pQ, *pK, *pV, *pP, *pC;
    cudaGetSymbolAddress(&pQ, g_Q);
    cudaGetSymbolAddress(&pK, g_K);
    cudaGetSymbolAddress(&pV, g_V);
    cudaGetSymbolAddress(&pP, g_P);
    cudaGetSymbolAddress(&pC, g_C);

    cudaFuncSetAttribute(flash_kernel,
                         cudaFuncAttributeMaxDynamicSharedMemorySize, FL_SMEM);
    cudaFuncSetAttribute(proj_kernel,
                         cudaFuncAttributeMaxDynamicSharedMemorySize, GB_SMEM);
    cudaFuncSetAttribute(bd_kernel,
                         cudaFuncAttributeMaxDynamicSharedMemorySize, GB_SMEM);

    const int Mq = BB * T1;     // 8192
    const int Mp = BB * NPOS;   // 16368

    ProjArgs pa;
    pa.A[0] = query; pa.W[0] = Wq; pa.bias[0] = bq;      pa.C[0] = (float*)pQ; pa.M[0] = Mq; pa.use3[0] = 1;
    pa.A[1] = key;   pa.W[1] = Wk; pa.bias[1] = bk;      pa.C[1] = (float*)pK; pa.M[1] = Mq; pa.use3[1] = 1;
    pa.A[2] = value; pa.W[2] = Wv; pa.bias[2] = bv;      pa.C[2] = (float*)pV; pa.M[2] = Mq; pa.use3[2] = 0;
    pa.A[3] = pos;   pa.W[3] = Wp; pa.bias[3] = nullptr; pa.C[3] = (float*)pP; pa.M[3] = Mp; pa.use3[3] = 1;
    proj_kernel<<<dim3(4, 128, 4), 256, GB_SMEM>>>(pa);

    bd_kernel<<<dim3(8, 4, BB * NH), 256, GB_SMEM>>>(pbv);

    flash_kernel<<<dim3(1, 4, BB * NH), 256, FL_SMEM>>>(pbu);

    ProjArgs po;
    for (int i = 0; i < 4; i++) {
        po.A[i] = (const float*)pC; po.W[i] = Wo; po.bias[i] = bo;
        po.C[i] = (float*)d_out; po.M[i] = Mq; po.use3[i] = 0;
    }
    proj_kernel<<<dim3(4, 64, 1), 256, GB_SMEM>>>(po);
}